// round 7
// baseline (speedup 1.0000x reference)
#include <cuda_runtime.h>
#include <math.h>
#include <stdint.h>

// Problem constants
#define SEQ   16384
#define DHID  1280
#define NH    16
#define HD    80
#define WSZ   64
#define NW    (SEQ / WSZ)      // 256
#define QKVN  (3 * DHID)       // 3840

// Scratch (device globals — no allocation allowed in kernel_launch)
__device__ float g_qkv[(size_t)SEQ * QKVN];    // 252 MB
__device__ float g_attn[(size_t)SEQ * DHID];   // 84 MB (tf32-rounded at store)
__device__ float g_w1_r[(size_t)QKVN * DHID];  // 19.7 MB tf32-rounded qkv_w
__device__ float g_w2_r[(size_t)DHID * DHID];  // 6.6 MB  tf32-rounded proj_w

__device__ __forceinline__ uint32_t f2tf32(float x) {
    uint32_t y;
    asm("cvt.rna.tf32.f32 %0, %1;" : "=r"(y) : "f"(x));
    return y;
}
__device__ __forceinline__ uint32_t tf32_of_bits(uint32_t raw) {
    return f2tf32(__uint_as_float(raw));
}

// ---------------------------------------------------------------------------
// Elementwise tf32 pre-rounding (vectorized, grid-stride) — weights only
// ---------------------------------------------------------------------------
__global__ void __launch_bounds__(256) round_tf32_kernel(
    const float4* __restrict__ in, float4* __restrict__ out, int n4)
{
    int i = blockIdx.x * blockDim.x + threadIdx.x;
    int stride = gridDim.x * blockDim.x;
    for (; i < n4; i += stride) {
        float4 v = in[i];
        float4 o;
        o.x = __uint_as_float(f2tf32(v.x));
        o.y = __uint_as_float(f2tf32(v.y));
        o.z = __uint_as_float(f2tf32(v.z));
        o.w = __uint_as_float(f2tf32(v.w));
        out[i] = o;
    }
}

// ---------------------------------------------------------------------------
// TF32 tensor-core GEMM (NT), 3-stage cp.async pipeline.
// B (weights) pre-rounded to tf32 -> loaded raw. A rounded at fragment load
// (identity when already tf32-rounded, e.g. proj GEMM's A).
// C[m,n] = sum_k A[m,k]*B[n,k] + bias[n]
// 128x128 block tile, BK=16, 256 threads (8 warps: 4 in m, 2 in n).
// Warp tile 32x64 = 2x8 m16n8k8 mma tiles.
// ---------------------------------------------------------------------------
#define ASTR 20          // smem row stride in words; conflict-free
#define STAGES 3
#define STG_W (128 * ASTR)   // words per matrix per stage

__device__ __forceinline__ void mma_tf32(float c[4], const uint32_t a[4],
                                         const uint32_t b[2]) {
    asm volatile(
        "mma.sync.aligned.m16n8k8.row.col.f32.tf32.tf32.f32 "
        "{%0,%1,%2,%3}, {%4,%5,%6,%7}, {%8,%9}, {%0,%1,%2,%3};"
        : "+f"(c[0]), "+f"(c[1]), "+f"(c[2]), "+f"(c[3])
        : "r"(a[0]), "r"(a[1]), "r"(a[2]), "r"(a[3]), "r"(b[0]), "r"(b[1]));
}

__device__ __forceinline__ void cp_async16(uint32_t saddr, const void* gptr) {
    asm volatile("cp.async.cg.shared.global [%0], [%1], 16;\n"
                 :: "r"(saddr), "l"(gptr));
}
__device__ __forceinline__ void cp_commit() {
    asm volatile("cp.async.commit_group;\n" ::: "memory");
}
template <int N>
__device__ __forceinline__ void cp_wait() {
    asm volatile("cp.async.wait_group %0;\n" :: "n"(N) : "memory");
}

__global__ void __launch_bounds__(256) tf32_gemm_nt_bias(
    const float* __restrict__ A, const float* __restrict__ B,
    const float* __restrict__ bias, float* __restrict__ C,
    int M, int N, int K)
{
    extern __shared__ uint32_t smg[];          // [STAGES][A|B][STG_W]
    uint32_t* As = smg;
    uint32_t* Bs = smg + STAGES * STG_W;

    const int tid  = threadIdx.x;
    const int lane = tid & 31;
    const int wid  = tid >> 5;
    const int warp_m = wid & 3;
    const int warp_n = wid >> 2;
    const int bm = blockIdx.y * 128;
    const int bn = blockIdx.x * 128;

    const int lrow = tid >> 1;
    const int lcol = (tid & 1) * 8;
    const float* Ap = A + (size_t)(bm + lrow) * K + lcol;
    const float* Bp = B + (size_t)(bn + lrow) * K + lcol;

    const uint32_t sA0 = (uint32_t)__cvta_generic_to_shared(
        &As[lrow * ASTR + lcol]);
    const uint32_t sB0 = (uint32_t)__cvta_generic_to_shared(
        &Bs[lrow * ASTR + lcol]);
    const uint32_t stageBytes = STG_W * 4;

    float acc[2][8][4];
    #pragma unroll
    for (int mi = 0; mi < 2; mi++)
        #pragma unroll
        for (int ni = 0; ni < 8; ni++)
            #pragma unroll
            for (int r = 0; r < 4; r++) acc[mi][ni][r] = 0.0f;

    const int niter = K / 16;

    // Preload stages 0..STAGES-2 (one commit group each)
    #pragma unroll
    for (int s = 0; s < STAGES - 1; ++s) {
        const float* Ap2 = Ap + (size_t)s * 16;
        const float* Bp2 = Bp + (size_t)s * 16;
        const uint32_t sa = sA0 + s * stageBytes;
        const uint32_t sb = sB0 + s * stageBytes;
        cp_async16(sa,      Ap2);
        cp_async16(sa + 16, Ap2 + 4);
        cp_async16(sb,      Bp2);
        cp_async16(sb + 16, Bp2 + 4);
        cp_commit();
    }

    for (int it = 0; it < niter; ++it) {
        const int cur = it % STAGES;

        cp_wait<STAGES - 2>();      // stage `it` landed
        __syncthreads();            // all warps done with stage it-1's slot

        // Issue stage it+STAGES-1 into the slot freed by stage it-1
        if (it + STAGES - 1 < niter) {
            const int nstage = it + STAGES - 1;
            const int nslot  = nstage % STAGES;
            const float* Ap2 = Ap + (size_t)nstage * 16;
            const float* Bp2 = Bp + (size_t)nstage * 16;
            const uint32_t sa = sA0 + nslot * stageBytes;
            const uint32_t sb = sB0 + nslot * stageBytes;
            cp_async16(sa,      Ap2);
            cp_async16(sa + 16, Ap2 + 4);
            cp_async16(sb,      Bp2);
            cp_async16(sb + 16, Bp2 + 4);
        }
        cp_commit();                // always commit to keep group indexing

        const uint32_t* Asc = As + cur * STG_W;
        const uint32_t* Bsc = Bs + cur * STG_W;
        #pragma unroll
        for (int k8 = 0; k8 < 2; ++k8) {
            const int kb = k8 * 8 + (lane & 3);
            uint32_t afrag[2][4];
            uint32_t bfrag[8][2];
            #pragma unroll
            for (int mi = 0; mi < 2; mi++) {
                const int r = warp_m * 32 + mi * 16 + (lane >> 2);
                afrag[mi][0] = tf32_of_bits(Asc[r * ASTR + kb]);
                afrag[mi][1] = tf32_of_bits(Asc[(r + 8) * ASTR + kb]);
                afrag[mi][2] = tf32_of_bits(Asc[r * ASTR + kb + 4]);
                afrag[mi][3] = tf32_of_bits(Asc[(r + 8) * ASTR + kb + 4]);
            }
            #pragma unroll
            for (int ni = 0; ni < 8; ni++) {
                const int c = warp_n * 64 + ni * 8 + (lane >> 2);
                bfrag[ni][0] = Bsc[c * ASTR + kb];        // pre-rounded
                bfrag[ni][1] = Bsc[c * ASTR + kb + 4];
            }
            #pragma unroll
            for (int mi = 0; mi < 2; mi++)
                #pragma unroll
                for (int ni = 0; ni < 8; ni++)
                    mma_tf32(acc[mi][ni], afrag[mi], bfrag[ni]);
        }
    }

    // Epilogue: + bias, float2 stores
    #pragma unroll
    for (int mi = 0; mi < 2; mi++) {
        const int row0 = bm + warp_m * 32 + mi * 16 + (lane >> 2);
        #pragma unroll
        for (int ni = 0; ni < 8; ni++) {
            const int col = bn + warp_n * 64 + ni * 8 + (lane & 3) * 2;
            const float b0 = bias[col], b1 = bias[col + 1];
            float2 o0 = { acc[mi][ni][0] + b0, acc[mi][ni][1] + b1 };
            float2 o1 = { acc[mi][ni][2] + b0, acc[mi][ni][3] + b1 };
            *(float2*)(C + (size_t)row0 * N + col)       = o0;
            *(float2*)(C + (size_t)(row0 + 8) * N + col) = o1;
        }
    }
}

// ---------------------------------------------------------------------------
// Per-(window, head) attention with fused RoPE.
// Output tf32-rounded at store (so proj GEMM's in-loop cvt is an identity).
// ---------------------------------------------------------------------------
#define PD 81

__global__ void __launch_bounds__(256) attn_kernel(
    const float* __restrict__ qkv, const float* __restrict__ cosv,
    const float* __restrict__ sinv, const float* __restrict__ mask,
    float* __restrict__ out)
{
    const int h = blockIdx.x;
    const int w = blockIdx.y;
    extern __shared__ float sm[];
    float* qs = sm;                 // 64*81
    float* ks = qs + WSZ * PD;
    float* vs = ks + WSZ * PD;
    float* sc = vs + WSZ * PD;      // 64*64

    const int tid = threadIdx.x;

    #pragma unroll
    for (int r = 0; r < 20; r++) {              // 64*80/256 = 20
        int idx = tid + 256 * r;
        int s = idx / HD, d = idx - s * HD;
        const float* base = qkv + (size_t)(w * WSZ + s) * QKVN + h * HD + d;
        qs[s * PD + d] = base[0];
        ks[s * PD + d] = base[DHID];
        vs[s * PD + d] = base[2 * DHID];
    }
    __syncthreads();

    float nq[20], nk[20];
    #pragma unroll
    for (int r = 0; r < 20; r++) {
        int idx = tid + 256 * r;
        int s = idx / HD, d = idx - s * HD;
        int gs = w * WSZ + s;
        float c  = cosv[(size_t)gs * HD + d];
        float sn = sinv[(size_t)gs * HD + d];
        int   pd  = (d < 40) ? d + 40 : d - 40;
        float sgn = (d < 40) ? -1.0f : 1.0f;
        nq[r] = qs[s * PD + d] * c + sgn * qs[s * PD + pd] * sn;
        nk[r] = ks[s * PD + d] * c + sgn * ks[s * PD + pd] * sn;
    }
    __syncthreads();
    #pragma unroll
    for (int r = 0; r < 20; r++) {
        int idx = tid + 256 * r;
        int s = idx / HD, d = idx - s * HD;
        qs[s * PD + d] = nq[r];
        ks[s * PD + d] = nk[r];
    }
    __syncthreads();

    const float scale = 0.11180339887498949f;   // 1/sqrt(80)
    const float* mk = mask + (size_t)w * (WSZ * WSZ);
    #pragma unroll
    for (int r = 0; r < 16; r++) {              // 4096/256
        int idx = tid + 256 * r;
        int i = idx >> 6, j = idx & 63;
        const float* qrow = qs + i * PD;
        const float* krow = ks + j * PD;
        float acc = 0.0f;
        #pragma unroll
        for (int d = 0; d < HD; d++)
            acc = fmaf(qrow[d], krow[d], acc);
        sc[idx] = acc * scale + mk[idx];
    }
    __syncthreads();

    const int wid = tid >> 5, lane = tid & 31;
    #pragma unroll
    for (int rr = 0; rr < 8; rr++) {
        int i = wid * 8 + rr;
        float v0 = sc[i * 64 + lane];
        float v1 = sc[i * 64 + lane + 32];
        float m = fmaxf(v0, v1);
        #pragma unroll
        for (int off = 16; off; off >>= 1)
            m = fmaxf(m, __shfl_xor_sync(0xFFFFFFFFu, m, off));
        float e0 = expf(v0 - m), e1 = expf(v1 - m);
        float ssum = e0 + e1;
        #pragma unroll
        for (int off = 16; off; off >>= 1)
            ssum += __shfl_xor_sync(0xFFFFFFFFu, ssum, off);
        float inv = 1.0f / ssum;
        sc[i * 64 + lane]      = e0 * inv;
        sc[i * 64 + lane + 32] = e1 * inv;
    }
    __syncthreads();

    #pragma unroll
    for (int r = 0; r < 20; r++) {
        int idx = tid + 256 * r;
        int i = idx / HD, d = idx - i * HD;
        const float* prow = sc + i * 64;
        float acc = 0.0f;
        #pragma unroll
        for (int j = 0; j < WSZ; j++)
            acc = fmaf(prow[j], vs[j * PD + d], acc);
        out[(size_t)(w * WSZ + i) * DHID + h * HD + d] =
            __uint_as_float(f2tf32(acc));
    }
}

// ---------------------------------------------------------------------------
// kernel_launch
// ---------------------------------------------------------------------------
extern "C" void kernel_launch(void* const* d_in, const int* in_sizes, int n_in,
                              void* d_out, int out_size)
{
    (void)in_sizes; (void)n_in; (void)out_size;
    const float* hs     = (const float*)d_in[0];
    const float* mask   = (const float*)d_in[1];
    const float* cosv   = (const float*)d_in[2];
    const float* sinv   = (const float*)d_in[3];
    const float* qkv_w  = (const float*)d_in[4];
    const float* qkv_b  = (const float*)d_in[5];
    const float* proj_w = (const float*)d_in[6];
    const float* proj_b = (const float*)d_in[7];
    float* out = (float*)d_out;

    float *qkv, *att, *w1_r, *w2_r;
    cudaGetSymbolAddress((void**)&qkv,  g_qkv);
    cudaGetSymbolAddress((void**)&att,  g_attn);
    cudaGetSymbolAddress((void**)&w1_r, g_w1_r);
    cudaGetSymbolAddress((void**)&w2_r, g_w2_r);

    // 0) Pre-round weights to tf32 values (stored as fp32)
    round_tf32_kernel<<<592, 256>>>((const float4*)qkv_w, (float4*)w1_r,
                                    QKVN * DHID / 4);
    round_tf32_kernel<<<592, 256>>>((const float4*)proj_w, (float4*)w2_r,
                                    DHID * DHID / 4);

    const int gemm_smem = STAGES * 2 * STG_W * 4;   // 61440 B
    cudaFuncSetAttribute(tf32_gemm_nt_bias,
                         cudaFuncAttributeMaxDynamicSharedMemorySize, gemm_smem);

    // 1) QKV GEMM + bias: [16384,1280] x [3840,1280]^T -> [16384,3840]
    tf32_gemm_nt_bias<<<dim3(QKVN / 128, SEQ / 128), 256, gemm_smem>>>(
        hs, w1_r, qkv_b, qkv, SEQ, QKVN, DHID);

    // 2) Windowed attention with fused RoPE (output tf32-rounded)
    size_t smem = (size_t)(3 * WSZ * PD + WSZ * WSZ) * sizeof(float);  // 78592 B
    cudaFuncSetAttribute(attn_kernel, cudaFuncAttributeMaxDynamicSharedMemorySize,
                         (int)smem);
    attn_kernel<<<dim3(NH, NW), 256, smem>>>(qkv, cosv, sinv, mask, att);

    // 3) Output projection: [16384,1280] x [1280,1280]^T + bias -> d_out
    tf32_gemm_nt_bias<<<dim3(DHID / 128, SEQ / 128), 256, gemm_smem>>>(
        att, w2_r, proj_b, out, SEQ, DHID, DHID);
}

// round 9
// speedup vs baseline: 1.5082x; 1.5082x over previous
#include <cuda_runtime.h>
#include <math.h>
#include <stdint.h>

// Problem constants
#define SEQ   16384
#define DHID  1280
#define NH    16
#define HD    80
#define WSZ   64
#define NW    (SEQ / WSZ)      // 256
#define QKVN  (3 * DHID)       // 3840

// Scratch (device globals — no allocation allowed in kernel_launch)
__device__ float g_qkv[(size_t)SEQ * QKVN];    // 252 MB
__device__ float g_attn[(size_t)SEQ * DHID];   // 84 MB

__device__ __forceinline__ uint32_t f2tf32(float x) {
    uint32_t y;
    asm("cvt.rna.tf32.f32 %0, %1;" : "=r"(y) : "f"(x));
    return y;
}
__device__ __forceinline__ uint32_t tf32_of_bits(uint32_t raw) {
    return f2tf32(__uint_as_float(raw));
}

// ---------------------------------------------------------------------------
// TF32 tensor-core GEMM (NT), BK=32, 2-stage cp.async pipeline.
// C[m,n] = sum_k A[m,k]*B[n,k] + bias[n]   (in-loop cvt.rna — round-4 numerics)
// 128x128 block tile, 256 threads (8 warps: 4 in m, 2 in n).
// Warp tile 32x64 = 2x8 m16n8k8 mma tiles, 4 k8-steps per stage.
// ---------------------------------------------------------------------------
#define BSTR 36                 // smem row stride in words (32 + 4 pad)
#define GSTG_W (128 * BSTR)     // words per matrix per stage (4608)
#define GSTG_B (GSTG_W * 4)     // bytes per matrix per stage
#define GEMM_SMEM (2 * 2 * GSTG_B)   // 73728 B

__device__ __forceinline__ void mma_tf32(float c[4], const uint32_t a[4],
                                         const uint32_t b[2]) {
    asm volatile(
        "mma.sync.aligned.m16n8k8.row.col.f32.tf32.tf32.f32 "
        "{%0,%1,%2,%3}, {%4,%5,%6,%7}, {%8,%9}, {%0,%1,%2,%3};"
        : "+f"(c[0]), "+f"(c[1]), "+f"(c[2]), "+f"(c[3])
        : "r"(a[0]), "r"(a[1]), "r"(a[2]), "r"(a[3]), "r"(b[0]), "r"(b[1]));
}

__device__ __forceinline__ void cp_async16(uint32_t saddr, const void* gptr) {
    asm volatile("cp.async.cg.shared.global [%0], [%1], 16;\n"
                 :: "r"(saddr), "l"(gptr));
}
__device__ __forceinline__ void cp_commit() {
    asm volatile("cp.async.commit_group;\n" ::: "memory");
}
template <int N>
__device__ __forceinline__ void cp_wait() {
    asm volatile("cp.async.wait_group %0;\n" :: "n"(N) : "memory");
}

__global__ void __launch_bounds__(256) tf32_gemm_nt_bias(
    const float* __restrict__ A, const float* __restrict__ B,
    const float* __restrict__ bias, float* __restrict__ C,
    int M, int N, int K)
{
    extern __shared__ uint32_t smg[];      // [2 stages][A|B][GSTG_W]
    uint32_t* As = smg;                    // 2 * GSTG_W
    uint32_t* Bs = smg + 2 * GSTG_W;

    const int tid  = threadIdx.x;
    const int lane = tid & 31;
    const int wid  = tid >> 5;
    const int warp_m = wid & 3;
    const int warp_n = wid >> 2;
    const int bm = blockIdx.y * 128;
    const int bn = blockIdx.x * 128;

    // Copy mapping: 1024 16B-segments per matrix per stage; 4 per thread.
    // seg = tid + 256*i; row = seg>>3 (0..127), cc = seg&7 (16B col in 128B row)
    const float* gA[4];
    const float* gB[4];
    uint32_t woff[4];                      // word offset in stage
    #pragma unroll
    for (int i = 0; i < 4; i++) {
        int seg = tid + 256 * i;
        int row = seg >> 3, cc = seg & 7;
        woff[i] = (uint32_t)(row * BSTR + cc * 4);
        gA[i] = A + (size_t)(bm + row) * K + cc * 4;
        gB[i] = B + (size_t)(bn + row) * K + cc * 4;
    }
    const uint32_t sA0 = (uint32_t)__cvta_generic_to_shared(As);
    const uint32_t sB0 = (uint32_t)__cvta_generic_to_shared(Bs);

    float acc[2][8][4];
    #pragma unroll
    for (int mi = 0; mi < 2; mi++)
        #pragma unroll
        for (int ni = 0; ni < 8; ni++)
            #pragma unroll
            for (int r = 0; r < 4; r++) acc[mi][ni][r] = 0.0f;

    const int niter = K / 32;

    // Preload stage 0
    #pragma unroll
    for (int i = 0; i < 4; i++) {
        cp_async16(sA0 + woff[i] * 4, gA[i]);
        cp_async16(sB0 + woff[i] * 4, gB[i]);
    }
    cp_commit();

    for (int it = 0; it < niter; ++it) {
        const int cur = it & 1;

        if (it + 1 < niter) {
            const int ns = (it + 1) & 1;
            #pragma unroll
            for (int i = 0; i < 4; i++) {
                cp_async16(sA0 + ns * GSTG_B + woff[i] * 4,
                           gA[i] + (size_t)(it + 1) * 32);
                cp_async16(sB0 + ns * GSTG_B + woff[i] * 4,
                           gB[i] + (size_t)(it + 1) * 32);
            }
            cp_commit();
            cp_wait<1>();       // stage `it` landed
        } else {
            cp_wait<0>();
        }
        __syncthreads();

        const uint32_t* Asc = As + cur * GSTG_W;
        const uint32_t* Bsc = Bs + cur * GSTG_W;
        #pragma unroll
        for (int k8 = 0; k8 < 4; ++k8) {
            const int kb = k8 * 8 + (lane & 3);
            uint32_t afrag[2][4];
            uint32_t bfrag[8][2];
            #pragma unroll
            for (int mi = 0; mi < 2; mi++) {
                const int r = warp_m * 32 + mi * 16 + (lane >> 2);
                afrag[mi][0] = tf32_of_bits(Asc[r * BSTR + kb]);
                afrag[mi][1] = tf32_of_bits(Asc[(r + 8) * BSTR + kb]);
                afrag[mi][2] = tf32_of_bits(Asc[r * BSTR + kb + 4]);
                afrag[mi][3] = tf32_of_bits(Asc[(r + 8) * BSTR + kb + 4]);
            }
            #pragma unroll
            for (int ni = 0; ni < 8; ni++) {
                const int c = warp_n * 64 + ni * 8 + (lane >> 2);
                bfrag[ni][0] = tf32_of_bits(Bsc[c * BSTR + kb]);
                bfrag[ni][1] = tf32_of_bits(Bsc[c * BSTR + kb + 4]);
            }
            #pragma unroll
            for (int mi = 0; mi < 2; mi++)
                #pragma unroll
                for (int ni = 0; ni < 8; ni++)
                    mma_tf32(acc[mi][ni], afrag[mi], bfrag[ni]);
        }
        __syncthreads();
    }

    // Epilogue: + bias, float2 stores
    #pragma unroll
    for (int mi = 0; mi < 2; mi++) {
        const int row0 = bm + warp_m * 32 + mi * 16 + (lane >> 2);
        #pragma unroll
        for (int ni = 0; ni < 8; ni++) {
            const int col = bn + warp_n * 64 + ni * 8 + (lane & 3) * 2;
            const float b0 = bias[col], b1 = bias[col + 1];
            float2 o0 = { acc[mi][ni][0] + b0, acc[mi][ni][1] + b1 };
            float2 o1 = { acc[mi][ni][2] + b0, acc[mi][ni][3] + b1 };
            *(float2*)(C + (size_t)row0 * N + col)       = o0;
            *(float2*)(C + (size_t)(row0 + 8) * N + col) = o1;
        }
    }
}

// ---------------------------------------------------------------------------
// Per-(window, head) attention. RoPE fused into load; register-microtiled
// scores (4x4, float4 smem loads) and P.V (4x5). 2 CTAs/SM.
// Per-element accumulation order identical to the baseline version.
// ---------------------------------------------------------------------------
#define PD2  84     // q/k/v row stride (words), mult of 4
#define SSTR 65     // scores row stride (words), odd -> conflict-free columns
#define ATTN_SMEM ((3 * WSZ * PD2 + WSZ * SSTR) * 4)   // 81152 B

__global__ void __launch_bounds__(256, 2) attn_kernel(
    const float* __restrict__ qkv, const float* __restrict__ cosv,
    const float* __restrict__ sinv, const float* __restrict__ mask,
    float* __restrict__ out)
{
    const int h = blockIdx.x;
    const int w = blockIdx.y;
    extern __shared__ float sm[];
    float* qs = sm;                    // 64*84
    float* ks = qs + WSZ * PD2;
    float* vs = ks + WSZ * PD2;
    float* sc = vs + WSZ * PD2;        // 64*65

    const int tid = threadIdx.x;

    // Load + RoPE in one pass (no register staging arrays)
    #pragma unroll
    for (int r = 0; r < 20; r++) {              // 64*80/256 = 20
        int idx = tid + 256 * r;
        int s = idx / HD, d = idx - s * HD;
        int gs = w * WSZ + s;
        const float* base = qkv + (size_t)gs * QKVN + h * HD;
        float c  = cosv[(size_t)gs * HD + d];
        float sn = sinv[(size_t)gs * HD + d];
        int   pd  = (d < 40) ? d + 40 : d - 40;
        float sgn = (d < 40) ? -1.0f : 1.0f;
        qs[s * PD2 + d] = base[d] * c + sgn * base[pd] * sn;
        ks[s * PD2 + d] = base[DHID + d] * c + sgn * base[DHID + pd] * sn;
        vs[s * PD2 + d] = base[2 * DHID + d];
    }
    __syncthreads();

    const float scale = 0.11180339887498949f;   // 1/sqrt(80)
    const float* mk = mask + (size_t)w * (WSZ * WSZ);
    const int ty = tid >> 4, tx = tid & 15;

    // Scores: thread computes rows i = ty+16r, cols j = tx+16c (4x4 tile)
    {
        float acc[4][4];
        #pragma unroll
        for (int r = 0; r < 4; r++)
            #pragma unroll
            for (int c = 0; c < 4; c++) acc[r][c] = 0.0f;

        #pragma unroll 4
        for (int d4 = 0; d4 < 20; d4++) {
            float4 qv[4], kv[4];
            #pragma unroll
            for (int r = 0; r < 4; r++)
                qv[r] = *(const float4*)&qs[(ty + 16 * r) * PD2 + d4 * 4];
            #pragma unroll
            for (int c = 0; c < 4; c++)
                kv[c] = *(const float4*)&ks[(tx + 16 * c) * PD2 + d4 * 4];
            #pragma unroll
            for (int r = 0; r < 4; r++)
                #pragma unroll
                for (int c = 0; c < 4; c++) {
                    float a = acc[r][c];
                    a = fmaf(qv[r].x, kv[c].x, a);
                    a = fmaf(qv[r].y, kv[c].y, a);
                    a = fmaf(qv[r].z, kv[c].z, a);
                    a = fmaf(qv[r].w, kv[c].w, a);
                    acc[r][c] = a;
                }
        }
        #pragma unroll
        for (int r = 0; r < 4; r++)
            #pragma unroll
            for (int c = 0; c < 4; c++) {
                int i = ty + 16 * r, j = tx + 16 * c;
                sc[i * SSTR + j] = acc[r][c] * scale + mk[i * 64 + j];
            }
    }
    __syncthreads();

    // Softmax: warp wid handles rows 8*wid..8*wid+7
    const int wid = tid >> 5, lane = tid & 31;
    #pragma unroll
    for (int rr = 0; rr < 8; rr++) {
        int i = wid * 8 + rr;
        float v0 = sc[i * SSTR + lane];
        float v1 = sc[i * SSTR + lane + 32];
        float m = fmaxf(v0, v1);
        #pragma unroll
        for (int off = 16; off; off >>= 1)
            m = fmaxf(m, __shfl_xor_sync(0xFFFFFFFFu, m, off));
        float e0 = expf(v0 - m), e1 = expf(v1 - m);
        float ssum = e0 + e1;
        #pragma unroll
        for (int off = 16; off; off >>= 1)
            ssum += __shfl_xor_sync(0xFFFFFFFFu, ssum, off);
        float inv = 1.0f / ssum;
        sc[i * SSTR + lane]      = e0 * inv;
        sc[i * SSTR + lane + 32] = e1 * inv;
    }
    __syncthreads();

    // O = P @ V: thread computes rows i = ty+16r, cols d = tx*5+c (4x5 tile)
    {
        float acco[4][5];
        #pragma unroll
        for (int r = 0; r < 4; r++)
            #pragma unroll
            for (int c = 0; c < 5; c++) acco[r][c] = 0.0f;

        #pragma unroll 4
        for (int j = 0; j < WSZ; j++) {
            float pv[4], vv[5];
            #pragma unroll
            for (int r = 0; r < 4; r++)
                pv[r] = sc[(ty + 16 * r) * SSTR + j];
            #pragma unroll
            for (int c = 0; c < 5; c++)
                vv[c] = vs[j * PD2 + tx * 5 + c];
            #pragma unroll
            for (int r = 0; r < 4; r++)
                #pragma unroll
                for (int c = 0; c < 5; c++)
                    acco[r][c] = fmaf(pv[r], vv[c], acco[r][c]);
        }
        #pragma unroll
        for (int r = 0; r < 4; r++) {
            int i = ty + 16 * r;
            float* op = out + (size_t)(w * WSZ + i) * DHID + h * HD + tx * 5;
            #pragma unroll
            for (int c = 0; c < 5; c++)
                op[c] = acco[r][c];
        }
    }
}

// ---------------------------------------------------------------------------
// kernel_launch: QKV GEMM -> attention(+RoPE) -> proj GEMM
// ---------------------------------------------------------------------------
extern "C" void kernel_launch(void* const* d_in, const int* in_sizes, int n_in,
                              void* d_out, int out_size)
{
    (void)in_sizes; (void)n_in; (void)out_size;
    const float* hs     = (const float*)d_in[0];
    const float* mask   = (const float*)d_in[1];
    const float* cosv   = (const float*)d_in[2];
    const float* sinv   = (const float*)d_in[3];
    const float* qkv_w  = (const float*)d_in[4];
    const float* qkv_b  = (const float*)d_in[5];
    const float* proj_w = (const float*)d_in[6];
    const float* proj_b = (const float*)d_in[7];
    float* out = (float*)d_out;

    float *qkv, *att;
    cudaGetSymbolAddress((void**)&qkv, g_qkv);
    cudaGetSymbolAddress((void**)&att, g_attn);

    cudaFuncSetAttribute(tf32_gemm_nt_bias,
                         cudaFuncAttributeMaxDynamicSharedMemorySize, GEMM_SMEM);
    cudaFuncSetAttribute(attn_kernel,
                         cudaFuncAttributeMaxDynamicSharedMemorySize, ATTN_SMEM);

    // 1) QKV GEMM + bias: [16384,1280] x [3840,1280]^T -> [16384,3840]
    tf32_gemm_nt_bias<<<dim3(QKVN / 128, SEQ / 128), 256, GEMM_SMEM>>>(
        hs, qkv_w, qkv_b, qkv, SEQ, QKVN, DHID);

    // 2) Windowed attention with fused RoPE
    attn_kernel<<<dim3(NH, NW), 256, ATTN_SMEM>>>(qkv, cosv, sinv, mask, att);

    // 3) Output projection: [16384,1280] x [1280,1280]^T + bias -> d_out
    tf32_gemm_nt_bias<<<dim3(DHID / 128, SEQ / 128), 256, GEMM_SMEM>>>(
        att, proj_w, proj_b, out, SEQ, DHID, DHID);
}